// round 14
// baseline (speedup 1.0000x reference)
#include <cuda_runtime.h>
#include <cstdint>
#include <cstddef>

#define B_ 4
#define T_ 4096
#define H_ 1024
// T_hist = 256 (fixed by setup_inputs)

// Device-global scratch (allocation-free). NOTE: g_h, g_W, g_K are stored with
// each 8-float column group permuted as s(l) = (l&3)*2 + (l>>2), i.e.
// (l0,l4,l1,l5,l2,l6,l3,l7). This makes every mma fragment pair (c, c+4)
// storage-adjacent -> LDS.64. inv(s) = (s>>1) + (s&1)*4.
__device__ float g_K[(size_t)B_ * T_ * H_];  // tf32-rounded K = h @ W^T (permuted cols)
__device__ float g_h[(size_t)B_ * T_ * H_];  // tf32-rounded h (permuted cols)
__device__ float g_W[(size_t)H_ * H_];       // tf32-rounded W (permuted cols)

__device__ __forceinline__ unsigned f2tf(float f) {
    unsigned u;
    asm("cvt.rna.tf32.f32 %0, %1;" : "=r"(u) : "f"(f));
    return u;
}

__device__ __forceinline__ void mma_tf32(float c[4], const unsigned a[4], const unsigned b[2]) {
    asm volatile(
        "mma.sync.aligned.m16n8k8.row.col.f32.tf32.tf32.f32 "
        "{%0,%1,%2,%3}, {%4,%5,%6,%7}, {%8,%9}, {%0,%1,%2,%3};"
        : "+f"(c[0]), "+f"(c[1]), "+f"(c[2]), "+f"(c[3])
        : "r"(a[0]), "r"(a[1]), "r"(a[2]), "r"(a[3]), "r"(b[0]), "r"(b[1]));
}

__device__ __forceinline__ void cp16(float* dst, const float* src) {
    unsigned d = (unsigned)__cvta_generic_to_shared(dst);
    asm volatile("cp.async.ca.shared.global [%0], [%1], 16;" ::"r"(d), "l"(src));
}
__device__ __forceinline__ void cp_commit() { asm volatile("cp.async.commit_group;"); }
__device__ __forceinline__ void cp_wait0() { asm volatile("cp.async.wait_group 0;"); }

__device__ __forceinline__ int sperm(int l) { return (l & 3) * 2 + (l >> 2); }

// ============================================================================
// Kernel 0: pre-round h and W to tf32 AND permute each 8-float group.
// group (l0..l7) -> storage (l0,l4,l1,l5, l2,l6,l3,l7)
// ============================================================================
__global__ __launch_bounds__(256)
void preround_kernel(const float* __restrict__ hin, const float* __restrict__ Wm) {
    const size_t NGH = (size_t)B_ * T_ * H_ / 8;  // 8-float groups in h
    const size_t NGW = (size_t)H_ * H_ / 8;
    size_t i = (size_t)blockIdx.x * blockDim.x + threadIdx.x;
    size_t stride = (size_t)gridDim.x * blockDim.x;
    for (size_t g = i; g < NGH; g += stride) {
        float4 a = ((const float4*)hin)[2 * g];
        float4 b = ((const float4*)hin)[2 * g + 1];
        float4 o0, o1;
        o0.x = __uint_as_float(f2tf(a.x)); o0.y = __uint_as_float(f2tf(b.x));
        o0.z = __uint_as_float(f2tf(a.y)); o0.w = __uint_as_float(f2tf(b.y));
        o1.x = __uint_as_float(f2tf(a.z)); o1.y = __uint_as_float(f2tf(b.z));
        o1.z = __uint_as_float(f2tf(a.w)); o1.w = __uint_as_float(f2tf(b.w));
        ((float4*)g_h)[2 * g] = o0;
        ((float4*)g_h)[2 * g + 1] = o1;
    }
    for (size_t g = i; g < NGW; g += stride) {
        float4 a = ((const float4*)Wm)[2 * g];
        float4 b = ((const float4*)Wm)[2 * g + 1];
        float4 o0, o1;
        o0.x = __uint_as_float(f2tf(a.x)); o0.y = __uint_as_float(f2tf(b.x));
        o0.z = __uint_as_float(f2tf(a.y)); o0.w = __uint_as_float(f2tf(b.y));
        o1.x = __uint_as_float(f2tf(a.z)); o1.y = __uint_as_float(f2tf(b.z));
        o1.z = __uint_as_float(f2tf(a.w)); o1.w = __uint_as_float(f2tf(b.w));
        ((float4*)g_W)[2 * g] = o0;
        ((float4*)g_W)[2 * g + 1] = o1;
    }
}

// ============================================================================
// Kernel 1: g_K = tf32(g_h @ g_W^T), 128x128x32 tile, 8 warps, 2 CTAs/SM.
// Row stride 40 -> conflict-free LDS.64 fragment pairs.
// ============================================================================
#define GST 40
#define GEMM_SMEM_FLOATS (2 * 2 * 128 * GST)  // 81,920 B -> 2 CTAs/SM

__global__ __launch_bounds__(256, 2)
void gemm_k_kernel() {
    extern __shared__ float sm[];
    const int m0 = blockIdx.y * 128;
    const int n0 = blockIdx.x * 128;
    const int tid = threadIdx.x;
    const int lane = tid & 31;
    const int warp = tid >> 5;
    const int wm = (warp & 1) * 64;
    const int wn = (warp >> 1) * 32;

    float acc[4][4][4];
#pragma unroll
    for (int i = 0; i < 4; i++)
#pragma unroll
        for (int j = 0; j < 4; j++)
#pragma unroll
            for (int k = 0; k < 4; k++) acc[i][j][k] = 0.f;

    auto load_tile = [&](int bi, int kt) {
        float* As = sm + bi * (128 * GST * 2);
        float* Bs = As + 128 * GST;
#pragma unroll
        for (int i = 0; i < 4; i++) {
            int f = tid + i * 256;  // 1024 quads: 128 rows x 8 quads
            int r = f >> 3;
            int c = (f & 7) * 4;
            cp16(&As[r * GST + c], &g_h[(size_t)(m0 + r) * H_ + kt + c]);
            cp16(&Bs[r * GST + c], &g_W[(size_t)(n0 + r) * H_ + kt + c]);
        }
        cp_commit();
    };

    const int c2 = 2 * (lane & 3);  // storage pair offset within 8-group

    load_tile(0, 0);
    for (int t = 0; t < 32; t++) {
        cp_wait0();
        __syncthreads();
        if (t + 1 < 32) load_tile((t + 1) & 1, (t + 1) * 32);
        const float* As = sm + (t & 1) * (128 * GST * 2);
        const float* Bs = As + 128 * GST;
#pragma unroll
        for (int ks = 0; ks < 32; ks += 8) {
            unsigned af[4][4], bf[4][2];
#pragma unroll
            for (int mt = 0; mt < 4; mt++) {
                int r = wm + mt * 16 + (lane >> 2);
                float2 v0 = *(const float2*)&As[r * GST + ks + c2];
                float2 v1 = *(const float2*)&As[(r + 8) * GST + ks + c2];
                af[mt][0] = __float_as_uint(v0.x);
                af[mt][2] = __float_as_uint(v0.y);
                af[mt][1] = __float_as_uint(v1.x);
                af[mt][3] = __float_as_uint(v1.y);
            }
#pragma unroll
            for (int nt = 0; nt < 4; nt++) {
                int rn = wn + nt * 8 + (lane >> 2);
                float2 w = *(const float2*)&Bs[rn * GST + ks + c2];
                bf[nt][0] = __float_as_uint(w.x);
                bf[nt][1] = __float_as_uint(w.y);
            }
#pragma unroll
            for (int mt = 0; mt < 4; mt++)
#pragma unroll
                for (int nt = 0; nt < 4; nt++) mma_tf32(acc[mt][nt], af[mt], bf[nt]);
        }
    }

    // epilogue: store tf32-rounded K in PERMUTED column layout.
    // logical pair (2l, 2l+1) -> storage cols s(2l), s(2l+1).
    const int l2 = 2 * (lane & 3);
    const int s0 = sperm(l2);
    const int s1 = sperm(l2 + 1);
#pragma unroll
    for (int mt = 0; mt < 4; mt++)
#pragma unroll
        for (int nt = 0; nt < 4; nt++) {
            int r = m0 + wm + mt * 16 + (lane >> 2);
            int grp = n0 + wn + nt * 8;
            g_K[(size_t)r * H_ + grp + s0] = __uint_as_float(f2tf(acc[mt][nt][0]));
            g_K[(size_t)r * H_ + grp + s1] = __uint_as_float(f2tf(acc[mt][nt][1]));
            g_K[(size_t)(r + 8) * H_ + grp + s0] = __uint_as_float(f2tf(acc[mt][nt][2]));
            g_K[(size_t)(r + 8) * H_ + grp + s1] = __uint_as_float(f2tf(acc[mt][nt][3]));
        }
}

// ============================================================================
// Kernel 2: banded attention (R10 structure; LDS.64 fragment loads).
// S token-columns stored permuted (written by phase 1, consumed by phase 3).
// ============================================================================
#define QT 64
#define SP 328   // S row stride: mod 32 == 8 -> conflict-free LDS.64
#define AST 40   // phase-1 tile row stride

#define P1BUF (64 * AST + 320 * AST)      // 15360 fl per stage
#define P3BUF 8448                         // Vt 32 x 264 per stage
#define TILES_FLOATS (2 * P1BUF)           // 30720 fl (phase3 16896 fits)
#define ATTN_SMEM_FLOATS (64 * SP + TILES_FLOATS + 64)  // 51776 fl = 207,104 B

__global__ __launch_bounds__(512, 1)
void attn_kernel(float* __restrict__ out) {
    extern __shared__ float smem[];
    float* S = smem;                       // 64 x 328 (token cols permuted)
    float* tiles = smem + 64 * SP;         // TILES_FLOATS
    float* rsum = tiles + TILES_FLOATS;    // 64

    const int b = blockIdx.y;
    const int q0 = blockIdx.x * QT;
    const int kstart = q0 - 256;
    const int tid = threadIdx.x;
    const int lane = tid & 31;
    const int warp = tid >> 5;  // 0..15

    const float* hb = g_h + (size_t)b * T_ * H_;   // permuted Q/V
    const float* Kb = g_K + (size_t)b * T_ * H_;   // permuted K

    const int c2 = 2 * (lane & 3);
    const int l2 = 2 * (lane & 3);
    const int sp0 = sperm(l2);
    const int sp1 = sperm(l2 + 1);

    // ---------------- Phase 1: S = Q K^T, full 64x320 in one k-sweep --------
    const int wm1 = (warp & 1) * 32;
    const int wn1 = (warp >> 1) * 40;   // 0..280 (multiple of 8)

    {
        float acc[2][5][4];
#pragma unroll
        for (int i = 0; i < 2; i++)
#pragma unroll
            for (int j = 0; j < 5; j++)
#pragma unroll
                for (int k = 0; k < 4; k++) acc[i][j][k] = 0.f;

        auto load1 = [&](int bi, int kt) {
            float* At = tiles + bi * P1BUF;      // 64 x 40
            float* Bt = At + 64 * AST;           // 320 x 40
            {
                int r = tid >> 3;
                int c = (tid & 7) * 4;
                cp16(&At[r * AST + c], &hb[(size_t)(q0 + r) * H_ + kt + c]);
            }
#pragma unroll
            for (int i = 0; i < 5; i++) {
                int f = tid + i * 512;
                int r = f >> 3;
                int c = (f & 7) * 4;
                int gr = kstart + r;
                gr = gr < 0 ? 0 : gr;  // clamp; masked in softmax
                cp16(&Bt[r * AST + c], &Kb[(size_t)gr * H_ + kt + c]);
            }
            cp_commit();
        };

        load1(0, 0);
        for (int t = 0; t < 32; t++) {
            cp_wait0();
            __syncthreads();
            if (t + 1 < 32) load1((t + 1) & 1, (t + 1) * 32);
            const float* At = tiles + (t & 1) * P1BUF;
            const float* Bt = At + 64 * AST;
#pragma unroll
            for (int ks = 0; ks < 32; ks += 8) {
                unsigned af[2][4], bf[5][2];
#pragma unroll
                for (int mt = 0; mt < 2; mt++) {
                    int r = wm1 + mt * 16 + (lane >> 2);
                    float2 v0 = *(const float2*)&At[r * AST + ks + c2];
                    float2 v1 = *(const float2*)&At[(r + 8) * AST + ks + c2];
                    af[mt][0] = __float_as_uint(v0.x);
                    af[mt][2] = __float_as_uint(v0.y);
                    af[mt][1] = __float_as_uint(v1.x);
                    af[mt][3] = __float_as_uint(v1.y);
                }
#pragma unroll
                for (int nt = 0; nt < 5; nt++) {
                    int rn = wn1 + nt * 8 + (lane >> 2);
                    float2 w = *(const float2*)&Bt[rn * AST + ks + c2];
                    bf[nt][0] = __float_as_uint(w.x);
                    bf[nt][1] = __float_as_uint(w.y);
                }
#pragma unroll
                for (int mt = 0; mt < 2; mt++)
#pragma unroll
                    for (int nt = 0; nt < 5; nt++) mma_tf32(acc[mt][nt], af[mt], bf[nt]);
            }
        }
        __syncthreads();
        // write raw scores into S, token cols permuted: logical (2l,2l+1) -> s0,s1
#pragma unroll
        for (int mt = 0; mt < 2; mt++)
#pragma unroll
            for (int nt = 0; nt < 5; nt++) {
                int r = wm1 + mt * 16 + (lane >> 2);
                int grp = wn1 + nt * 8;
                S[r * SP + grp + sp0] = acc[mt][nt][0];
                S[r * SP + grp + sp1] = acc[mt][nt][1];
                S[(r + 8) * SP + grp + sp0] = acc[mt][nt][2];
                S[(r + 8) * SP + grp + sp1] = acc[mt][nt][3];
            }
    }
    __syncthreads();

    // ---------------- Phase 2: masked softmax (warp per 4 rows) -------------
    // storage col c -> logical token offset (c&~7) + inv(c&7), inv(s)=(s>>1)+(s&1)*4
#pragma unroll
    for (int rr = 0; rr < 4; rr++) {
        int r = warp * 4 + rr;
        int iq = q0 + r;
        float v[10];
        float mx = -1e30f;
#pragma unroll
        for (int cc = 0; cc < 10; cc++) {
            int c = lane + cc * 32;
            int s = c & 7;
            int j = kstart + (c & ~7) + (s >> 1) + (s & 1) * 4;
            bool valid = (j >= 0) && (j <= iq) && (j >= iq - 255);
            v[cc] = valid ? S[r * SP + c] * 0.03125f : -1e30f;
            mx = fmaxf(mx, v[cc]);
        }
#pragma unroll
        for (int o = 16; o > 0; o >>= 1) mx = fmaxf(mx, __shfl_xor_sync(0xffffffffu, mx, o));
        float sum = 0.f;
#pragma unroll
        for (int cc = 0; cc < 10; cc++) {
            int c = lane + cc * 32;
            float p = (v[cc] > -1e29f) ? __expf(v[cc] - mx) : 0.f;
            sum += p;
            S[r * SP + c] = __uint_as_float(f2tf(p));  // stays in permuted slot
        }
#pragma unroll
        for (int o = 16; o > 0; o >>= 1) sum += __shfl_xor_sync(0xffffffffu, sum, o);
        if (lane == 0) rsum[r] = 1.0f / sum;
    }
    __syncthreads();

    // ---------------- Phase 3: O = P V, 64x256 per round (4 rounds) ---------
    const int wm3 = (warp & 1) * 32;
    const int wn3 = (warp >> 1) * 32;
    const int t0 = (kstart < 0) ? ((-kstart) >> 5) : 0;

    for (int hc = 0; hc < 4; hc++) {
        float acc[2][4][4];
#pragma unroll
        for (int i = 0; i < 2; i++)
#pragma unroll
            for (int j = 0; j < 4; j++)
#pragma unroll
                for (int k = 0; k < 4; k++) acc[i][j][k] = 0.f;

        auto load3 = [&](int bi, int tt) {
            float* Vt = tiles + bi * P3BUF;  // 32 x 264 [k][n]
#pragma unroll
            for (int i = 0; i < 4; i++) {
                int f = tid + i * 512;
                int k = f >> 6;
                int n4 = (f & 63) * 4;
                int gr = kstart + tt * 32 + k;
                gr = gr < 0 ? 0 : gr;
                cp16(&Vt[k * 264 + n4], &hb[(size_t)gr * H_ + hc * 256 + n4]);
            }
            cp_commit();
        };

        load3(t0 & 1, t0);
        for (int t = t0; t < 10; t++) {
            cp_wait0();
            __syncthreads();
            if (t + 1 < 10) load3((t + 1) & 1, t + 1);
            const float* Vt = tiles + (t & 1) * P3BUF;
            int kt = t * 32;
#pragma unroll
            for (int ks = 0; ks < 32; ks += 8) {
                unsigned af[2][4], bf[4][2];
#pragma unroll
                for (int mt = 0; mt < 2; mt++) {
                    int r = wm3 + mt * 16 + (lane >> 2);
                    float2 v0 = *(const float2*)&S[r * SP + kt + ks + c2];
                    float2 v1 = *(const float2*)&S[(r + 8) * SP + kt + ks + c2];
                    af[mt][0] = __float_as_uint(v0.x);
                    af[mt][2] = __float_as_uint(v0.y);
                    af[mt][1] = __float_as_uint(v1.x);
                    af[mt][3] = __float_as_uint(v1.y);
                }
#pragma unroll
                for (int nt = 0; nt < 4; nt++) {
                    int kk = ks + (lane & 3);
                    int n = wn3 + nt * 8 + (lane >> 2);
                    bf[nt][0] = __float_as_uint(Vt[kk * 264 + n]);
                    bf[nt][1] = __float_as_uint(Vt[(kk + 4) * 264 + n]);
                }
#pragma unroll
                for (int mt = 0; mt < 2; mt++)
#pragma unroll
                    for (int nt = 0; nt < 4; nt++) mma_tf32(acc[mt][nt], af[mt], bf[nt]);
            }
        }
        __syncthreads();
        // epilogue: normalize, UN-PERMUTE V's h-cols, store.
        // mma n = storage col; storage pair (2l, 2l+1) -> logical (l, l+4).
#pragma unroll
        for (int mt = 0; mt < 2; mt++) {
            int r = wm3 + mt * 16 + (lane >> 2);
            float s0f = rsum[r];
            float s1f = rsum[r + 8];
            int ll = lane & 3;
#pragma unroll
            for (int nt = 0; nt < 4; nt++) {
                int grp = hc * 256 + wn3 + nt * 8;
                size_t o0 = ((size_t)b * T_ + q0 + r) * H_ + grp;
                out[o0 + ll] = acc[mt][nt][0] * s0f;
                out[o0 + ll + 4] = acc[mt][nt][1] * s0f;
                out[o0 + (size_t)8 * H_ + ll] = acc[mt][nt][2] * s1f;
                out[o0 + (size_t)8 * H_ + ll + 4] = acc[mt][nt][3] * s1f;
            }
        }
    }
}

// ============================================================================
extern "C" void kernel_launch(void* const* d_in, const int* in_sizes, int n_in,
                              void* d_out, int out_size) {
    const float* h = (const float*)d_in[0];
    const float* W = (const float*)d_in[1];
    // d_in[2] = T_hist (always 256)
    float* out = (float*)d_out;

    preround_kernel<<<2048, 256>>>(h, W);

    cudaFuncSetAttribute(gemm_k_kernel, cudaFuncAttributeMaxDynamicSharedMemorySize,
                         GEMM_SMEM_FLOATS * 4);
    gemm_k_kernel<<<dim3(8, 128), 256, GEMM_SMEM_FLOATS * 4>>>();

    cudaFuncSetAttribute(attn_kernel, cudaFuncAttributeMaxDynamicSharedMemorySize,
                         ATTN_SMEM_FLOATS * 4);
    attn_kernel<<<dim3(T_ / QT, B_), 512, ATTN_SMEM_FLOATS * 4>>>(out);
}

// round 15
// speedup vs baseline: 1.1018x; 1.1018x over previous
#include <cuda_runtime.h>
#include <cstdint>
#include <cstddef>

#define B_ 4
#define T_ 4096
#define H_ 1024
// T_hist = 256 (fixed by setup_inputs)

// Device-global scratch (allocation-free).
// g_h / g_W: tf32-rounded, with each 8-float group along the h (contraction)
// dim permuted as s(l) = (l&3)*2 + (l>>2)  -> (l0,l4,l1,l5,l2,l6,l3,l7).
// Used ONLY by the gemm (both operands permuted identically -> identical dot
// products, fragment pairs (c, c+4) storage-adjacent -> LDS.64).
// g_hu: tf32-rounded UNPERMUTED copy of h, used by the attention kernel.
// g_K: tf32-rounded K, plain layout (gemm epilogue unchanged from R10).
__device__ float g_K[(size_t)B_ * T_ * H_];
__device__ float g_h[(size_t)B_ * T_ * H_];
__device__ float g_hu[(size_t)B_ * T_ * H_];
__device__ float g_W[(size_t)H_ * H_];

__device__ __forceinline__ unsigned f2tf(float f) {
    unsigned u;
    asm("cvt.rna.tf32.f32 %0, %1;" : "=r"(u) : "f"(f));
    return u;
}

__device__ __forceinline__ void mma_tf32(float c[4], const unsigned a[4], const unsigned b[2]) {
    asm volatile(
        "mma.sync.aligned.m16n8k8.row.col.f32.tf32.tf32.f32 "
        "{%0,%1,%2,%3}, {%4,%5,%6,%7}, {%8,%9}, {%0,%1,%2,%3};"
        : "+f"(c[0]), "+f"(c[1]), "+f"(c[2]), "+f"(c[3])
        : "r"(a[0]), "r"(a[1]), "r"(a[2]), "r"(a[3]), "r"(b[0]), "r"(b[1]));
}

__device__ __forceinline__ void cp16(float* dst, const float* src) {
    unsigned d = (unsigned)__cvta_generic_to_shared(dst);
    asm volatile("cp.async.ca.shared.global [%0], [%1], 16;" ::"r"(d), "l"(src));
}
__device__ __forceinline__ void cp_commit() { asm volatile("cp.async.commit_group;"); }
__device__ __forceinline__ void cp_wait0() { asm volatile("cp.async.wait_group 0;"); }

// ============================================================================
// Kernel 0: tf32 pre-round. Writes permuted g_h/g_W (gemm) and plain g_hu (attn).
// ============================================================================
__global__ __launch_bounds__(256)
void preround_kernel(const float* __restrict__ hin, const float* __restrict__ Wm) {
    const size_t NGH = (size_t)B_ * T_ * H_ / 8;  // 8-float groups
    const size_t NGW = (size_t)H_ * H_ / 8;
    size_t i = (size_t)blockIdx.x * blockDim.x + threadIdx.x;
    size_t stride = (size_t)gridDim.x * blockDim.x;
    for (size_t g = i; g < NGH; g += stride) {
        float4 a = ((const float4*)hin)[2 * g];
        float4 b = ((const float4*)hin)[2 * g + 1];
        a.x = __uint_as_float(f2tf(a.x)); a.y = __uint_as_float(f2tf(a.y));
        a.z = __uint_as_float(f2tf(a.z)); a.w = __uint_as_float(f2tf(a.w));
        b.x = __uint_as_float(f2tf(b.x)); b.y = __uint_as_float(f2tf(b.y));
        b.z = __uint_as_float(f2tf(b.z)); b.w = __uint_as_float(f2tf(b.w));
        // plain copy for attention
        ((float4*)g_hu)[2 * g] = a;
        ((float4*)g_hu)[2 * g + 1] = b;
        // permuted copy for gemm: (a.x,b.x,a.y,b.y | a.z,b.z,a.w,b.w)
        float4 o0 = make_float4(a.x, b.x, a.y, b.y);
        float4 o1 = make_float4(a.z, b.z, a.w, b.w);
        ((float4*)g_h)[2 * g] = o0;
        ((float4*)g_h)[2 * g + 1] = o1;
    }
    for (size_t g = i; g < NGW; g += stride) {
        float4 a = ((const float4*)Wm)[2 * g];
        float4 b = ((const float4*)Wm)[2 * g + 1];
        a.x = __uint_as_float(f2tf(a.x)); a.y = __uint_as_float(f2tf(a.y));
        a.z = __uint_as_float(f2tf(a.z)); a.w = __uint_as_float(f2tf(a.w));
        b.x = __uint_as_float(f2tf(b.x)); b.y = __uint_as_float(f2tf(b.y));
        b.z = __uint_as_float(f2tf(b.z)); b.w = __uint_as_float(f2tf(b.w));
        float4 o0 = make_float4(a.x, b.x, a.y, b.y);
        float4 o1 = make_float4(a.z, b.z, a.w, b.w);
        ((float4*)g_W)[2 * g] = o0;
        ((float4*)g_W)[2 * g + 1] = o1;
    }
}

// ============================================================================
// Kernel 1: g_K = tf32(g_h @ g_W^T), 128x128x32 tile, 8 warps, 2 CTAs/SM.
// Contraction dim permuted in storage -> all fragment loads are LDS.64
// (24 -> 12 shared loads per ks-step). Register contents per mma are
// bit-identical to R10. Epilogue unchanged (plain g_K layout).
// ============================================================================
#define GST 40  // tile row stride: LDS.64 phase covers all 32 banks once
#define GEMM_SMEM_FLOATS (2 * 2 * 128 * GST)  // 81,920 B -> 2 CTAs/SM

__global__ __launch_bounds__(256, 2)
void gemm_k_kernel() {
    extern __shared__ float sm[];
    const int m0 = blockIdx.y * 128;
    const int n0 = blockIdx.x * 128;
    const int tid = threadIdx.x;
    const int lane = tid & 31;
    const int warp = tid >> 5;
    const int wm = (warp & 1) * 64;
    const int wn = (warp >> 1) * 32;

    float acc[4][4][4];
#pragma unroll
    for (int i = 0; i < 4; i++)
#pragma unroll
        for (int j = 0; j < 4; j++)
#pragma unroll
            for (int k = 0; k < 4; k++) acc[i][j][k] = 0.f;

    auto load_tile = [&](int bi, int kt) {
        float* As = sm + bi * (2 * 128 * GST);
        float* Bs = As + 128 * GST;
#pragma unroll
        for (int i = 0; i < 4; i++) {
            int f = tid + i * 256;  // 1024 quads: 128 rows x 8 quads
            int r = f >> 3;
            int c = (f & 7) * 4;
            cp16(&As[r * GST + c], &g_h[(size_t)(m0 + r) * H_ + kt + c]);
            cp16(&Bs[r * GST + c], &g_W[(size_t)(n0 + r) * H_ + kt + c]);
        }
        cp_commit();
    };

    const int c2 = 2 * (lane & 3);  // storage offset of logical pair (c, c+4)

    load_tile(0, 0);
    for (int t = 0; t < 32; t++) {
        cp_wait0();
        __syncthreads();
        if (t + 1 < 32) load_tile((t + 1) & 1, (t + 1) * 32);
        const float* As = sm + (t & 1) * (2 * 128 * GST);
        const float* Bs = As + 128 * GST;
#pragma unroll
        for (int ks = 0; ks < 32; ks += 8) {
            unsigned af[4][4], bf[4][2];
#pragma unroll
            for (int mt = 0; mt < 4; mt++) {
                int r = wm + mt * 16 + (lane >> 2);
                float2 v0 = *(const float2*)&As[r * GST + ks + c2];         // (c, c+4)
                float2 v1 = *(const float2*)&As[(r + 8) * GST + ks + c2];
                af[mt][0] = __float_as_uint(v0.x);
                af[mt][2] = __float_as_uint(v0.y);
                af[mt][1] = __float_as_uint(v1.x);
                af[mt][3] = __float_as_uint(v1.y);
            }
#pragma unroll
            for (int nt = 0; nt < 4; nt++) {
                int rn = wn + nt * 8 + (lane >> 2);
                float2 w = *(const float2*)&Bs[rn * GST + ks + c2];
                bf[nt][0] = __float_as_uint(w.x);
                bf[nt][1] = __float_as_uint(w.y);
            }
#pragma unroll
            for (int mt = 0; mt < 4; mt++)
#pragma unroll
                for (int nt = 0; nt < 4; nt++) mma_tf32(acc[mt][nt], af[mt], bf[nt]);
        }
    }

    // epilogue: identical to R10 (plain layout, coalesced float2 stores)
#pragma unroll
    for (int mt = 0; mt < 4; mt++)
#pragma unroll
        for (int nt = 0; nt < 4; nt++) {
            int r = m0 + wm + mt * 16 + (lane >> 2);
            int c = n0 + wn + nt * 8 + (lane & 3) * 2;
            *(float2*)&g_K[(size_t)r * H_ + c] =
                make_float2(__uint_as_float(f2tf(acc[mt][nt][0])),
                            __uint_as_float(f2tf(acc[mt][nt][1])));
            *(float2*)&g_K[(size_t)(r + 8) * H_ + c] =
                make_float2(__uint_as_float(f2tf(acc[mt][nt][2])),
                            __uint_as_float(f2tf(acc[mt][nt][3])));
        }
}

// ============================================================================
// Kernel 2: banded attention — byte-identical to the R10 418.6us winner,
// reading the unpermuted tf32 copy g_hu.
// ============================================================================
#define QT 64
#define SP 324  // S row stride: (324m + c)%32 = (4m + c)%32 -> conflict-free

#define P1BUF 13824
#define TILES_FLOATS (2 * P1BUF)
#define ATTN_SMEM_FLOATS (64 * SP + TILES_FLOATS + 64)  // 48448 fl = 193,792 B

__global__ __launch_bounds__(512, 1)
void attn_kernel(float* __restrict__ out) {
    extern __shared__ float smem[];
    float* S = smem;                       // 64 x 324
    float* tiles = smem + 64 * SP;         // TILES_FLOATS
    float* rsum = tiles + TILES_FLOATS;    // 64

    const int b = blockIdx.y;
    const int q0 = blockIdx.x * QT;
    const int kstart = q0 - 256;
    const int tid = threadIdx.x;
    const int lane = tid & 31;
    const int warp = tid >> 5;  // 0..15

    const float* hb = g_hu + (size_t)b * T_ * H_;  // pre-rounded Q/V (plain)
    const float* Kb = g_K + (size_t)b * T_ * H_;   // pre-rounded K (plain)

    // ---------------- Phase 1: S = Q K^T, full 64x320 in one k-sweep --------
    const int wm1 = (warp & 1) * 32;
    const int wn1 = (warp >> 1) * 40;   // 0..280

    {
        float acc[2][5][4];
#pragma unroll
        for (int i = 0; i < 2; i++)
#pragma unroll
            for (int j = 0; j < 5; j++)
#pragma unroll
                for (int k = 0; k < 4; k++) acc[i][j][k] = 0.f;

        auto load1 = [&](int bi, int kt) {
            float* At = tiles + bi * P1BUF;      // 64 x 36
            float* Bt = At + 2304;               // 320 x 36
            {
                int r = tid >> 3;
                int c = (tid & 7) * 4;
                cp16(&At[r * 36 + c], &hb[(size_t)(q0 + r) * H_ + kt + c]);
            }
#pragma unroll
            for (int i = 0; i < 5; i++) {
                int f = tid + i * 512;
                int r = f >> 3;
                int c = (f & 7) * 4;
                int gr = kstart + r;
                gr = gr < 0 ? 0 : gr;  // clamp; masked in softmax
                cp16(&Bt[r * 36 + c], &Kb[(size_t)gr * H_ + kt + c]);
            }
            cp_commit();
        };

        load1(0, 0);
        for (int t = 0; t < 32; t++) {
            cp_wait0();
            __syncthreads();
            if (t + 1 < 32) load1((t + 1) & 1, (t + 1) * 32);
            const float* At = tiles + (t & 1) * P1BUF;
            const float* Bt = At + 2304;
#pragma unroll
            for (int ks = 0; ks < 32; ks += 8) {
                unsigned af[2][4], bf[5][2];
#pragma unroll
                for (int mt = 0; mt < 2; mt++) {
                    int r = wm1 + mt * 16 + (lane >> 2);
                    int c = ks + (lane & 3);
                    af[mt][0] = __float_as_uint(At[r * 36 + c]);
                    af[mt][1] = __float_as_uint(At[(r + 8) * 36 + c]);
                    af[mt][2] = __float_as_uint(At[r * 36 + c + 4]);
                    af[mt][3] = __float_as_uint(At[(r + 8) * 36 + c + 4]);
                }
#pragma unroll
                for (int nt = 0; nt < 5; nt++) {
                    int rn = wn1 + nt * 8 + (lane >> 2);
                    int c = ks + (lane & 3);
                    bf[nt][0] = __float_as_uint(Bt[rn * 36 + c]);
                    bf[nt][1] = __float_as_uint(Bt[rn * 36 + c + 4]);
                }
#pragma unroll
                for (int mt = 0; mt < 2; mt++)
#pragma unroll
                    for (int nt = 0; nt < 5; nt++) mma_tf32(acc[mt][nt], af[mt], bf[nt]);
            }
        }
        __syncthreads();
#pragma unroll
        for (int mt = 0; mt < 2; mt++)
#pragma unroll
            for (int nt = 0; nt < 5; nt++) {
                int r = wm1 + mt * 16 + (lane >> 2);
                int c = wn1 + nt * 8 + (lane & 3) * 2;
                S[r * SP + c] = acc[mt][nt][0];
                S[r * SP + c + 1] = acc[mt][nt][1];
                S[(r + 8) * SP + c] = acc[mt][nt][2];
                S[(r + 8) * SP + c + 1] = acc[mt][nt][3];
            }
    }
    __syncthreads();

    // ---------------- Phase 2: masked softmax (warp per 4 rows) -------------
#pragma unroll
    for (int rr = 0; rr < 4; rr++) {
        int r = warp * 4 + rr;
        int iq = q0 + r;
        float v[10];
        float mx = -1e30f;
#pragma unroll
        for (int cc = 0; cc < 10; cc++) {
            int c = lane + cc * 32;
            int j = kstart + c;
            bool valid = (j >= 0) && (j <= iq) && (j >= iq - 255);
            v[cc] = valid ? S[r * SP + c] * 0.03125f : -1e30f;
            mx = fmaxf(mx, v[cc]);
        }
#pragma unroll
        for (int o = 16; o > 0; o >>= 1) mx = fmaxf(mx, __shfl_xor_sync(0xffffffffu, mx, o));
        float sum = 0.f;
#pragma unroll
        for (int cc = 0; cc < 10; cc++) {
            int c = lane + cc * 32;
            float p = (v[cc] > -1e29f) ? __expf(v[cc] - mx) : 0.f;
            sum += p;
            S[r * SP + c] = __uint_as_float(f2tf(p));
        }
#pragma unroll
        for (int o = 16; o > 0; o >>= 1) sum += __shfl_xor_sync(0xffffffffu, sum, o);
        if (lane == 0) rsum[r] = 1.0f / sum;
    }
    __syncthreads();

    // ---------------- Phase 3: O = P V, 64x256 per round (4 rounds) ---------
    const int wm3 = (warp & 1) * 32;
    const int wn3 = (warp >> 1) * 32;
    const int t0 = (kstart < 0) ? ((-kstart) >> 5) : 0;

    for (int hc = 0; hc < 4; hc++) {
        float acc[2][4][4];
#pragma unroll
        for (int i = 0; i < 2; i++)
#pragma unroll
            for (int j = 0; j < 4; j++)
#pragma unroll
                for (int k = 0; k < 4; k++) acc[i][j][k] = 0.f;

        auto load3 = [&](int bi, int tt) {
            float* Vt = tiles + bi * 8448;  // 32 x 264 [k][n]
#pragma unroll
            for (int i = 0; i < 4; i++) {
                int f = tid + i * 512;
                int k = f >> 6;
                int n4 = (f & 63) * 4;
                int gr = kstart + tt * 32 + k;
                gr = gr < 0 ? 0 : gr;
                cp16(&Vt[k * 264 + n4], &hb[(size_t)gr * H_ + hc * 256 + n4]);
            }
            cp_commit();
        };

        load3(t0 & 1, t0);
        for (int t = t0; t < 10; t++) {
            cp_wait0();
            __syncthreads();
            if (t + 1 < 10) load3((t + 1) & 1, t + 1);
            const float* Vt = tiles + (t & 1) * 8448;
            int kt = t * 32;
#pragma unroll
            for (int ks = 0; ks < 32; ks += 8) {
                unsigned af[2][4], bf[4][2];
#pragma unroll
                for (int mt = 0; mt < 2; mt++) {
                    int r = wm3 + mt * 16 + (lane >> 2);
                    int c = kt + ks + (lane & 3);
                    af[mt][0] = __float_as_uint(S[r * SP + c]);
                    af[mt][1] = __float_as_uint(S[(r + 8) * SP + c]);
                    af[mt][2] = __float_as_uint(S[r * SP + c + 4]);
                    af[mt][3] = __float_as_uint(S[(r + 8) * SP + c + 4]);
                }
#pragma unroll
                for (int nt = 0; nt < 4; nt++) {
                    int kk = ks + (lane & 3);
                    int n = wn3 + nt * 8 + (lane >> 2);
                    bf[nt][0] = __float_as_uint(Vt[kk * 264 + n]);
                    bf[nt][1] = __float_as_uint(Vt[(kk + 4) * 264 + n]);
                }
#pragma unroll
                for (int mt = 0; mt < 2; mt++)
#pragma unroll
                    for (int nt = 0; nt < 4; nt++) mma_tf32(acc[mt][nt], af[mt], bf[nt]);
            }
        }
        __syncthreads();
#pragma unroll
        for (int mt = 0; mt < 2; mt++) {
            int r = wm3 + mt * 16 + (lane >> 2);
            float s0 = rsum[r];
            float s1 = rsum[r + 8];
#pragma unroll
            for (int nt = 0; nt < 4; nt++) {
                int c = hc * 256 + wn3 + nt * 8 + (lane & 3) * 2;
                size_t o0 = ((size_t)b * T_ + q0 + r) * H_ + c;
                *(float2*)&out[o0] = make_float2(acc[mt][nt][0] * s0, acc[mt][nt][1] * s0);
                *(float2*)&out[o0 + (size_t)8 * H_] =
                    make_float2(acc[mt][nt][2] * s1, acc[mt][nt][3] * s1);
            }
        }
    }
}

// ============================================================================
extern "C" void kernel_launch(void* const* d_in, const int* in_sizes, int n_in,
                              void* d_out, int out_size) {
    const float* h = (const float*)d_in[0];
    const float* W = (const float*)d_in[1];
    // d_in[2] = T_hist (always 256)
    float* out = (float*)d_out;

    preround_kernel<<<2048, 256>>>(h, W);

    cudaFuncSetAttribute(gemm_k_kernel, cudaFuncAttributeMaxDynamicSharedMemorySize,
                         GEMM_SMEM_FLOATS * 4);
    gemm_k_kernel<<<dim3(8, 128), 256, GEMM_SMEM_FLOATS * 4>>>();

    cudaFuncSetAttribute(attn_kernel, cudaFuncAttributeMaxDynamicSharedMemorySize,
                         ATTN_SMEM_FLOATS * 4);
    attn_kernel<<<dim3(T_ / QT, B_), 512, ATTN_SMEM_FLOATS * 4>>>(out);
}